// round 11
// baseline (speedup 1.0000x reference)
#include <cuda_runtime.h>
#include <cuda_bf16.h>

#define N_NODES 100000
#define N_EDGES 1600000
#define D 32
#define ED 8
#define FULL 0xffffffffu
#define UN 4                 // 4-edge groups per tile -> 16 edges per warp-iter
#define TILE (UN * 4)        // 16; N_EDGES % 16 == 0 -> no tail handling

// Ping-pong node features + per-layer aggregation buffers (zeroed once).
__device__ float g_buf0[N_NODES * D];
__device__ float g_buf1[N_NODES * D];
__device__ float g_agg[3][N_NODES * D];

// ---------------------------------------------------------------------------
// Zero ALL three aggregation buffers in one pass (runs once per call).
// ---------------------------------------------------------------------------
__global__ void zero_all_kernel() {
    const int n4 = 3 * N_NODES * D / 4;
    float4* p = reinterpret_cast<float4*>(&g_agg[0][0]);
    float4 z = make_float4(0.f, 0.f, 0.f, 0.f);
    for (int i = blockIdx.x * blockDim.x + threadIdx.x; i < n4;
         i += gridDim.x * blockDim.x) {
        p[i] = z;
    }
}

// ---------------------------------------------------------------------------
// Edge kernel: 16 edges per warp-iteration (4 independent 4-edge groups),
// MLP=4 on gathers and REDs, next-tile index prefetch.
//   lane layout: g = lane>>3 edge-in-quad, c = lane&7 column quad (4c..4c+3).
// Index fetch: ONE LDG.32 per tile — lanes 0-15 read src[e+lane], lanes
// 16-31 read dst[e+lane-16]; per-group ids extracted via SHFL. This keeps
// the whole tile's indices in 1 register (+1 for the prefetched tile),
// targeting <=102 regs so 5 blocks/SM are resident (20 warps, +25% vs R8).
// ---------------------------------------------------------------------------
__global__ __launch_bounds__(128, 5) void edge_kernel(
    const float* __restrict__ x_ext, int x_sel, int layer,
    const float* __restrict__ edge_attr,
    const float* __restrict__ We,   // layer slice: [8, 32]
    const float* __restrict__ be,   // layer slice: [32]
    const int*   __restrict__ edge_index)  // [2, E]: src then dst
{
    const float* x = (x_sel == 0) ? x_ext : (x_sel == 1 ? g_buf0 : g_buf1);
    float* agg = &g_agg[layer][0];

    const int lane = threadIdx.x & 31;
    const int c    = lane & 7;
    const int g    = lane >> 3;
    const int wid  = (blockIdx.x * blockDim.x + threadIdx.x) >> 5;
    const int nw   = (gridDim.x * blockDim.x) >> 5;

    float4 wv[ED];
#pragma unroll
    for (int k = 0; k < ED; k++)
        wv[k] = *reinterpret_cast<const float4*>(We + k * D + c * 4);
    const float4 bias = *reinterpret_cast<const float4*>(be + c * 4);

    int e = wid * TILE;
    if (e >= N_EDGES) return;

    // lanes 0-15: src[e + lane]; lanes 16-31: dst[e + lane - 16]
    const int idx_off = (lane < 16) ? lane : (N_EDGES - 16 + lane);

    int iv = __ldg(edge_index + e + idx_off);

    const int stride = nw * TILE;
    for (; e < N_EDGES; e += stride) {
        // 4 independent gathers issue immediately (indices resident).
        float4 xv[UN];
#pragma unroll
        for (int u = 0; u < UN; u++) {
            const int s = __shfl_sync(FULL, iv, u * 4 + g);
            xv[u] = __ldg(reinterpret_cast<const float4*>(
                x + (size_t)s * D + c * 4));
        }

        // Attr loads (chain-free, coalesced 128B per group).
        float av[UN];
#pragma unroll
        for (int u = 0; u < UN; u++)
            av[u] = __ldg(edge_attr + (size_t)(e + u * 4) * ED + lane);

        // Prefetch next tile's indices (wrapped on last iteration).
        const int ne = e + stride;
        const int nc = (ne < N_EDGES) ? ne : 0;
        const int niv = __ldg(edge_index + nc + idx_off);

        // Extract dst ids (SHFL only, no memory dependency).
        int dd[UN];
#pragma unroll
        for (int u = 0; u < UN; u++)
            dd[u] = __shfl_sync(FULL, iv, 16 + u * 4 + g);

        float4 a[UN];
#pragma unroll
        for (int u = 0; u < UN; u++) a[u] = bias;
#pragma unroll
        for (int k = 0; k < ED; k++) {
            const float4 wk = wv[k];
#pragma unroll
            for (int u = 0; u < UN; u++) {
                const float f = __shfl_sync(FULL, av[u], (g << 3) | k);
                a[u].x = fmaf(f, wk.x, a[u].x);
                a[u].y = fmaf(f, wk.y, a[u].y);
                a[u].z = fmaf(f, wk.z, a[u].z);
                a[u].w = fmaf(f, wk.w, a[u].w);
            }
        }

#pragma unroll
        for (int u = 0; u < UN; u++) {
            float4 m;
            m.x = fmaxf(xv[u].x + a[u].x, 0.0f);
            m.y = fmaxf(xv[u].y + a[u].y, 0.0f);
            m.z = fmaxf(xv[u].z + a[u].z, 0.0f);
            m.w = fmaxf(xv[u].w + a[u].w, 0.0f);
            float* p = agg + (size_t)dd[u] * D + c * 4;
            asm volatile("red.global.add.v4.f32 [%0], {%1,%2,%3,%4};"
                         :: "l"(p), "f"(m.x), "f"(m.y), "f"(m.z), "f"(m.w)
                         : "memory");
        }

        iv = niv;
    }
}

// ---------------------------------------------------------------------------
// Node kernel: one warp per node (~12us/layer, unchanged).
// ---------------------------------------------------------------------------
__global__ __launch_bounds__(256) void node_kernel(
    const float* __restrict__ x_ext, int x_sel, int layer,
    float* __restrict__ out_ext, int out_sel,
    const float* __restrict__ W,    // [32, 32]
    const float* __restrict__ b)    // [32]
{
    const float* x  = (x_sel == 0) ? x_ext : (x_sel == 1 ? g_buf0 : g_buf1);
    float* out = (out_sel == 0) ? out_ext : (out_sel == 1 ? g_buf0 : g_buf1);
    const float* agg = &g_agg[layer][0];

    const int lane = threadIdx.x & 31;
    const int wid  = (blockIdx.x * blockDim.x + threadIdx.x) >> 5;
    const int nw   = (gridDim.x * blockDim.x) >> 5;

    float w[D];
#pragma unroll
    for (int k = 0; k < D; k++) w[k] = W[k * D + lane];
    const float bias = b[lane];

    for (int node = wid; node < N_NODES; node += nw) {
        const float h = x[node * D + lane] + agg[node * D + lane];
        float acc = bias;
#pragma unroll
        for (int k = 0; k < D; k++)
            acc = fmaf(__shfl_sync(FULL, h, k), w[k], acc);
        out[node * D + lane] = fmaxf(acc, 0.01f * acc);  // leaky_relu 0.01
    }
}

// ---------------------------------------------------------------------------
extern "C" void kernel_launch(void* const* d_in, const int* in_sizes, int n_in,
                              void* d_out, int out_size)
{
    const float* x   = (const float*)d_in[0];   // [N, 32]
    const float* ea  = (const float*)d_in[1];   // [E, 8]
    const float* W   = (const float*)d_in[2];   // [3, 32, 32]
    const float* b   = (const float*)d_in[3];   // [3, 32]
    const float* We  = (const float*)d_in[4];   // [3, 8, 32]
    const float* be  = (const float*)d_in[5];   // [3, 32]
    const int*   ei  = (const int*)d_in[6];     // [2, E] int32
    float* out = (float*)d_out;

    const int x_sels[3]   = {0, 1, 2};
    const int out_sels[3] = {1, 2, 0};

    zero_all_kernel<<<1184, 256>>>();
    for (int l = 0; l < 3; l++) {
        edge_kernel<<<2368, 128>>>(
            x, x_sels[l], l, ea, We + l * ED * D, be + l * D, ei);
        node_kernel<<<592, 256>>>(
            x, x_sels[l], l, out, out_sels[l], W + l * D * D, b + l * D);
    }
}

// round 12
// speedup vs baseline: 1.1191x; 1.1191x over previous
#include <cuda_runtime.h>
#include <cuda_bf16.h>
#include <cstdint>

#define N_NODES 100000
#define N_EDGES 1600000
#define D 32
#define ED 8
#define FULL 0xffffffffu
#define UN 4                 // 4-edge groups per tile -> 16 edges per warp-iter
#define TILE (UN * 4)        // N_EDGES % 16 == 0

// f32x2 packed-math helpers (PTX-only; ptxas never fuses these from C++).
#define PACKF2(out, lo, hi) \
    asm("mov.b64 %0, {%1, %2};" : "=l"(out) \
        : "r"(__float_as_uint(lo)), "r"(__float_as_uint(hi)))
#define FMA_F32X2(d, a, b, c) \
    asm("fma.rn.f32x2 %0, %1, %2, %3;" : "=l"(d) : "l"(a), "l"(b), "l"(c))
#define UNPACKF2(lo, hi, in) do { \
    uint32_t _l, _h; \
    asm("mov.b64 {%0, %1}, %2;" : "=r"(_l), "=r"(_h) : "l"(in)); \
    (lo) = __uint_as_float(_l); (hi) = __uint_as_float(_h); } while (0)

// Ping-pong node features + per-layer aggregation buffers (zeroed once).
__device__ float g_buf0[N_NODES * D];
__device__ float g_buf1[N_NODES * D];
__device__ float g_agg[3][N_NODES * D];

// ---------------------------------------------------------------------------
// Zero ALL three aggregation buffers in one pass (runs once per call).
// ---------------------------------------------------------------------------
__global__ void zero_all_kernel() {
    const int n4 = 3 * N_NODES * D / 4;
    float4* p = reinterpret_cast<float4*>(&g_agg[0][0]);
    float4 z = make_float4(0.f, 0.f, 0.f, 0.f);
    for (int i = blockIdx.x * blockDim.x + threadIdx.x; i < n4;
         i += gridDim.x * blockDim.x) {
        p[i] = z;
    }
}

// ---------------------------------------------------------------------------
// Edge kernel (R8 base, f32x2 k-loop): 16 edges per warp-iteration,
// 4 independent 4-edge groups (MLP=4 on gathers and REDs), next-tile index
// prefetch. lane layout: g = lane>>3 edge-in-quad, c = lane&7 column quad.
// Embedding loop uses fma.rn.f32x2 on (x,y)/(z,w) register pairs:
// per (k,u) = 1 pack + 2 FMA2 instead of 4 FFMA (-32 issue slots/tile).
// Persistent grid: 592 blocks (4/SM, single wave).
// ---------------------------------------------------------------------------
__global__ __launch_bounds__(128, 4) void edge_kernel(
    const float* __restrict__ x_ext, int x_sel, int layer,
    const float* __restrict__ edge_attr,
    const float* __restrict__ We,   // layer slice: [8, 32]
    const float* __restrict__ be,   // layer slice: [32]
    const int*   __restrict__ src,
    const int*   __restrict__ dst)
{
    const float* x = (x_sel == 0) ? x_ext : (x_sel == 1 ? g_buf0 : g_buf1);
    float* agg = &g_agg[layer][0];

    const int lane = threadIdx.x & 31;
    const int c    = lane & 7;
    const int g    = lane >> 3;
    const int wid  = (blockIdx.x * blockDim.x + threadIdx.x) >> 5;
    const int nw   = (gridDim.x * blockDim.x) >> 5;

    // Weight column quads as packed f32x2 pairs: (x,y) and (z,w) per k.
    uint64_t wxy[ED], wzw[ED];
#pragma unroll
    for (int k = 0; k < ED; k++) {
        const float4 wv = *reinterpret_cast<const float4*>(We + k * D + c * 4);
        PACKF2(wxy[k], wv.x, wv.y);
        PACKF2(wzw[k], wv.z, wv.w);
    }
    uint64_t bxy, bzw;
    {
        const float4 bv = *reinterpret_cast<const float4*>(be + c * 4);
        PACKF2(bxy, bv.x, bv.y);
        PACKF2(bzw, bv.z, bv.w);
    }

    int e = wid * TILE;
    if (e >= N_EDGES) return;

    // Prologue: first tile's indices (N_EDGES % 16 == 0, tiles full).
    int s[UN], d[UN];
#pragma unroll
    for (int u = 0; u < UN; u++) {
        s[u] = __ldg(src + e + u * 4 + g);
        d[u] = __ldg(dst + e + u * 4 + g);
    }

    const int stride = nw * TILE;
    for (; e < N_EDGES; e += stride) {
        // 4 independent gathers issue immediately (indices resident).
        float4 xv[UN];
#pragma unroll
        for (int u = 0; u < UN; u++)
            xv[u] = __ldg(reinterpret_cast<const float4*>(
                x + (size_t)s[u] * D + c * 4));

        // Attr loads (chain-free, coalesced 128B per group).
        float av[UN];
#pragma unroll
        for (int u = 0; u < UN; u++)
            av[u] = __ldg(edge_attr + (size_t)(e + u * 4) * ED + lane);

        // Prefetch next tile's indices (wrapped on last iteration).
        const int ne = e + stride;
        const int nc = (ne < N_EDGES) ? ne : 0;
        int ns[UN], nd[UN];
#pragma unroll
        for (int u = 0; u < UN; u++) {
            ns[u] = __ldg(src + nc + u * 4 + g);
            nd[u] = __ldg(dst + nc + u * 4 + g);
        }

        // Packed-FMA embedding: a[u] = be + sum_k attr_k * We[k]
        uint64_t axy[UN], azw[UN];
#pragma unroll
        for (int u = 0; u < UN; u++) { axy[u] = bxy; azw[u] = bzw; }
#pragma unroll
        for (int k = 0; k < ED; k++) {
#pragma unroll
            for (int u = 0; u < UN; u++) {
                const float f = __shfl_sync(FULL, av[u], (g << 3) | k);
                uint64_t pf;
                PACKF2(pf, f, f);
                FMA_F32X2(axy[u], pf, wxy[k], axy[u]);
                FMA_F32X2(azw[u], pf, wzw[k], azw[u]);
            }
        }

#pragma unroll
        for (int u = 0; u < UN; u++) {
            float ax, ay, az, aw;
            UNPACKF2(ax, ay, axy[u]);
            UNPACKF2(az, aw, azw[u]);
            float4 m;
            m.x = fmaxf(xv[u].x + ax, 0.0f);
            m.y = fmaxf(xv[u].y + ay, 0.0f);
            m.z = fmaxf(xv[u].z + az, 0.0f);
            m.w = fmaxf(xv[u].w + aw, 0.0f);
            float* p = agg + (size_t)d[u] * D + c * 4;
            asm volatile("red.global.add.v4.f32 [%0], {%1,%2,%3,%4};"
                         :: "l"(p), "f"(m.x), "f"(m.y), "f"(m.z), "f"(m.w)
                         : "memory");
        }

#pragma unroll
        for (int u = 0; u < UN; u++) { s[u] = ns[u]; d[u] = nd[u]; }
    }
}

// ---------------------------------------------------------------------------
// Node kernel: one warp per node (~12us/layer, unchanged).
// ---------------------------------------------------------------------------
__global__ __launch_bounds__(256) void node_kernel(
    const float* __restrict__ x_ext, int x_sel, int layer,
    float* __restrict__ out_ext, int out_sel,
    const float* __restrict__ W,    // [32, 32]
    const float* __restrict__ b)    // [32]
{
    const float* x  = (x_sel == 0) ? x_ext : (x_sel == 1 ? g_buf0 : g_buf1);
    float* out = (out_sel == 0) ? out_ext : (out_sel == 1 ? g_buf0 : g_buf1);
    const float* agg = &g_agg[layer][0];

    const int lane = threadIdx.x & 31;
    const int wid  = (blockIdx.x * blockDim.x + threadIdx.x) >> 5;
    const int nw   = (gridDim.x * blockDim.x) >> 5;

    float w[D];
#pragma unroll
    for (int k = 0; k < D; k++) w[k] = W[k * D + lane];
    const float bias = b[lane];

    for (int node = wid; node < N_NODES; node += nw) {
        const float h = x[node * D + lane] + agg[node * D + lane];
        float acc = bias;
#pragma unroll
        for (int k = 0; k < D; k++)
            acc = fmaf(__shfl_sync(FULL, h, k), w[k], acc);
        out[node * D + lane] = fmaxf(acc, 0.01f * acc);  // leaky_relu 0.01
    }
}

// ---------------------------------------------------------------------------
extern "C" void kernel_launch(void* const* d_in, const int* in_sizes, int n_in,
                              void* d_out, int out_size)
{
    const float* x   = (const float*)d_in[0];   // [N, 32]
    const float* ea  = (const float*)d_in[1];   // [E, 8]
    const float* W   = (const float*)d_in[2];   // [3, 32, 32]
    const float* b   = (const float*)d_in[3];   // [3, 32]
    const float* We  = (const float*)d_in[4];   // [3, 8, 32]
    const float* be  = (const float*)d_in[5];   // [3, 32]
    const int*   ei  = (const int*)d_in[6];     // [2, E] int32
    float* out = (float*)d_out;

    const int* src = ei;
    const int* dst = ei + N_EDGES;

    const int x_sels[3]   = {0, 1, 2};
    const int out_sels[3] = {1, 2, 0};

    zero_all_kernel<<<1184, 256>>>();
    for (int l = 0; l < 3; l++) {
        edge_kernel<<<592, 128>>>(   // persistent: 4 blocks/SM, single wave
            x, x_sels[l], l, ea, We + l * ED * D, be + l * D, src, dst);
        node_kernel<<<592, 256>>>(
            x, x_sels[l], l, out, out_sels[l], W + l * D * D, b + l * D);
    }
}

// round 13
// speedup vs baseline: 1.1497x; 1.0274x over previous
#include <cuda_runtime.h>
#include <cuda_bf16.h>
#include <cstdint>

#define N_NODES 100000
#define N_EDGES 1600000
#define D 32
#define ED 8
#define FULL 0xffffffffu
#define UN 4                 // 4-edge groups per tile -> 16 edges per warp-iter
#define TILE (UN * 4)        // N_EDGES % 16 == 0

// f32x2 packed-math helpers (PTX-only; ptxas never fuses these from C++).
#define PACKF2(out, lo, hi) \
    asm("mov.b64 %0, {%1, %2};" : "=l"(out) \
        : "r"(__float_as_uint(lo)), "r"(__float_as_uint(hi)))
#define FMA_F32X2(d, a, b, c) \
    asm("fma.rn.f32x2 %0, %1, %2, %3;" : "=l"(d) : "l"(a), "l"(b), "l"(c))
#define UNPACKF2(lo, hi, in) do { \
    uint32_t _l, _h; \
    asm("mov.b64 {%0, %1}, %2;" : "=r"(_l), "=r"(_h) : "l"(in)); \
    (lo) = __uint_as_float(_l); (hi) = __uint_as_float(_h); } while (0)

// Ping-pong node features + per-layer aggregation buffers (zeroed once).
__device__ float g_buf0[N_NODES * D];
__device__ float g_buf1[N_NODES * D];
__device__ float g_agg[3][N_NODES * D];

// ---------------------------------------------------------------------------
// Zero ALL three aggregation buffers in one pass (runs once per call).
// ---------------------------------------------------------------------------
__global__ void zero_all_kernel() {
    const int n4 = 3 * N_NODES * D / 4;
    float4* p = reinterpret_cast<float4*>(&g_agg[0][0]);
    float4 z = make_float4(0.f, 0.f, 0.f, 0.f);
    for (int i = blockIdx.x * blockDim.x + threadIdx.x; i < n4;
         i += gridDim.x * blockDim.x) {
        p[i] = z;
    }
}

// ---------------------------------------------------------------------------
// Edge kernel (R12 base + consolidated loads): 16 edges per warp-iteration,
// 4 independent 4-edge groups (MLP=4 gathers/REDs), next-tile idx prefetch,
// f32x2 packed FMA embedding loop.
//   lane layout: g = lane>>3 edge-in-quad, c = lane&7 column quad.
// Idx: ONE lane-spread LDG.32 per tile (lanes 0-15 src, 16-31 dst; 2
// wavefronts vs 8 scalar loads), extracted via SHFL into s[]/d[] arrays.
// Attr: ONE LDG.128 per tile (lane holds 4 consecutive floats of the
// 128-float tile attr block), distributed via SHFL at use.
// ---------------------------------------------------------------------------
__global__ __launch_bounds__(128, 4) void edge_kernel(
    const float* __restrict__ x_ext, int x_sel, int layer,
    const float* __restrict__ edge_attr,
    const float* __restrict__ We,   // layer slice: [8, 32]
    const float* __restrict__ be,   // layer slice: [32]
    const int*   __restrict__ edge_index)  // [2, E]: src rows then dst rows
{
    const float* x = (x_sel == 0) ? x_ext : (x_sel == 1 ? g_buf0 : g_buf1);
    float* agg = &g_agg[layer][0];

    const int lane = threadIdx.x & 31;
    const int c    = lane & 7;
    const int g    = lane >> 3;
    const int wid  = (blockIdx.x * blockDim.x + threadIdx.x) >> 5;
    const int nw   = (gridDim.x * blockDim.x) >> 5;

    // Weight column quads as packed f32x2 pairs: (x,y) and (z,w) per k.
    uint64_t wxy[ED], wzw[ED];
#pragma unroll
    for (int k = 0; k < ED; k++) {
        const float4 wv = *reinterpret_cast<const float4*>(We + k * D + c * 4);
        PACKF2(wxy[k], wv.x, wv.y);
        PACKF2(wzw[k], wv.z, wv.w);
    }
    uint64_t bxy, bzw;
    {
        const float4 bv = *reinterpret_cast<const float4*>(be + c * 4);
        PACKF2(bxy, bv.x, bv.y);
        PACKF2(bzw, bv.z, bv.w);
    }

    int e = wid * TILE;
    if (e >= N_EDGES) return;

    // lanes 0-15: src[e+lane]; lanes 16-31: dst[e+lane-16]
    const int idx_off = (lane < 16) ? lane : (N_EDGES - 16 + lane);

    // Prologue: first tile's indices in ONE load, extracted to arrays.
    int s[UN], d[UN];
    {
        const int iv = __ldg(edge_index + e + idx_off);
#pragma unroll
        for (int u = 0; u < UN; u++) {
            s[u] = __shfl_sync(FULL, iv, u * 4 + g);
            d[u] = __shfl_sync(FULL, iv, 16 + u * 4 + g);
        }
    }

    const int stride = nw * TILE;
    for (; e < N_EDGES; e += stride) {
        // 4 independent gathers issue immediately (indices resident).
        float4 xv[UN];
#pragma unroll
        for (int u = 0; u < UN; u++)
            xv[u] = __ldg(reinterpret_cast<const float4*>(
                x + (size_t)s[u] * D + c * 4));

        // Whole tile's 128 attr floats in one LDG.128 (lane owns 4).
        const float4 av4 = __ldg(
            reinterpret_cast<const float4*>(edge_attr + (size_t)e * ED) + lane);

        // Prefetch next tile's indices (wrapped on last iteration).
        const int ne = e + stride;
        const int nc = (ne < N_EDGES) ? ne : 0;
        const int niv = __ldg(edge_index + nc + idx_off);

        // Packed-FMA embedding: a[u] = be + sum_k attr_k * We[k]
        // attr k of edge (4u+g) lives in lane 8u+2g+(k>>2), component k&3.
        uint64_t axy[UN], azw[UN];
#pragma unroll
        for (int u = 0; u < UN; u++) { axy[u] = bxy; azw[u] = bzw; }
#pragma unroll
        for (int k = 0; k < ED; k++) {
            const float comp = ((k & 3) == 0) ? av4.x
                             : ((k & 3) == 1) ? av4.y
                             : ((k & 3) == 2) ? av4.z : av4.w;
#pragma unroll
            for (int u = 0; u < UN; u++) {
                const float f =
                    __shfl_sync(FULL, comp, u * 8 + g * 2 + (k >> 2));
                uint64_t pf;
                PACKF2(pf, f, f);
                FMA_F32X2(axy[u], pf, wxy[k], axy[u]);
                FMA_F32X2(azw[u], pf, wzw[k], azw[u]);
            }
        }

#pragma unroll
        for (int u = 0; u < UN; u++) {
            float ax, ay, az, aw;
            UNPACKF2(ax, ay, axy[u]);
            UNPACKF2(az, aw, azw[u]);
            float4 m;
            m.x = fmaxf(xv[u].x + ax, 0.0f);
            m.y = fmaxf(xv[u].y + ay, 0.0f);
            m.z = fmaxf(xv[u].z + az, 0.0f);
            m.w = fmaxf(xv[u].w + aw, 0.0f);
            float* p = agg + (size_t)d[u] * D + c * 4;
            asm volatile("red.global.add.v4.f32 [%0], {%1,%2,%3,%4};"
                         :: "l"(p), "f"(m.x), "f"(m.y), "f"(m.z), "f"(m.w)
                         : "memory");
        }

        // Extract next tile's ids into the arrays for the next iteration.
#pragma unroll
        for (int u = 0; u < UN; u++) {
            s[u] = __shfl_sync(FULL, niv, u * 4 + g);
            d[u] = __shfl_sync(FULL, niv, 16 + u * 4 + g);
        }
    }
}

// ---------------------------------------------------------------------------
// Node kernel: 2 nodes per warp, lane = (node gn = lane>>4, column pair
// c2 = lane&15 -> cols 2c2, 2c2+1), f32x2 FMAs. Half the issue slots of the
// 1-node form and MLP=2 on the x/agg loads.
// ---------------------------------------------------------------------------
__global__ __launch_bounds__(128) void node_kernel(
    const float* __restrict__ x_ext, int x_sel, int layer,
    float* __restrict__ out_ext, int out_sel,
    const float* __restrict__ W,    // [32, 32]
    const float* __restrict__ b)    // [32]
{
    const float* x  = (x_sel == 0) ? x_ext : (x_sel == 1 ? g_buf0 : g_buf1);
    float* out = (out_sel == 0) ? out_ext : (out_sel == 1 ? g_buf0 : g_buf1);
    const float* agg = &g_agg[layer][0];

    const int lane = threadIdx.x & 31;
    const int c2   = lane & 15;     // column pair: cols 2c2, 2c2+1
    const int gn   = lane >> 4;     // node within the warp's pair
    const int wid  = (blockIdx.x * blockDim.x + threadIdx.x) >> 5;
    const int nw   = (gridDim.x * blockDim.x) >> 5;

    // W column pair per k, packed f32x2. 32 pairs = 64 regs.
    uint64_t w2[D];
#pragma unroll
    for (int k = 0; k < D; k++) {
        const float2 wv = *reinterpret_cast<const float2*>(W + k * D + c2 * 2);
        PACKF2(w2[k], wv.x, wv.y);
    }
    uint64_t b2;
    {
        const float2 bv = *reinterpret_cast<const float2*>(b + c2 * 2);
        PACKF2(b2, bv.x, bv.y);
    }

    // N_NODES is even: every warp-iteration covers 2 full nodes.
    for (int n2 = wid * 2; n2 < N_NODES; n2 += nw * 2) {
        const int node = n2 + gn;
        const float2 xv = *reinterpret_cast<const float2*>(
            x + (size_t)node * D + c2 * 2);
        const float2 ag = *reinterpret_cast<const float2*>(
            agg + (size_t)node * D + c2 * 2);
        const float h0 = xv.x + ag.x;   // col 2c2
        const float h1 = xv.y + ag.y;   // col 2c2+1

        uint64_t acc = b2;
#pragma unroll
        for (int k = 0; k < D; k++) {
            // h_k of node gn: lane (gn<<4) + (k>>1), component k&1.
            const float hk = (k & 1) ? h1 : h0;
            const float f = __shfl_sync(FULL, hk, (gn << 4) + (k >> 1));
            uint64_t pf;
            PACKF2(pf, f, f);
            FMA_F32X2(acc, pf, w2[k], acc);
        }
        float o0, o1;
        UNPACKF2(o0, o1, acc);
        float2 o;
        o.x = fmaxf(o0, 0.01f * o0);    // leaky_relu 0.01
        o.y = fmaxf(o1, 0.01f * o1);
        *reinterpret_cast<float2*>(out + (size_t)node * D + c2 * 2) = o;
    }
}

// ---------------------------------------------------------------------------
extern "C" void kernel_launch(void* const* d_in, const int* in_sizes, int n_in,
                              void* d_out, int out_size)
{
    const float* x   = (const float*)d_in[0];   // [N, 32]
    const float* ea  = (const float*)d_in[1];   // [E, 8]
    const float* W   = (const float*)d_in[2];   // [3, 32, 32]
    const float* b   = (const float*)d_in[3];   // [3, 32]
    const float* We  = (const float*)d_in[4];   // [3, 8, 32]
    const float* be  = (const float*)d_in[5];   // [3, 32]
    const int*   ei  = (const int*)d_in[6];     // [2, E] int32
    float* out = (float*)d_out;

    const int x_sels[3]   = {0, 1, 2};
    const int out_sels[3] = {1, 2, 0};

    zero_all_kernel<<<1184, 256>>>();
    for (int l = 0; l < 3; l++) {
        edge_kernel<<<592, 128>>>(   // persistent: 4 blocks/SM, single wave
            x, x_sels[l], l, ea, We + l * ED * D, be + l * D, ei);
        node_kernel<<<1184, 128>>>(
            x, x_sels[l], l, out, out_sels[l], W + l * D * D, b + l * D);
    }
}

// round 14
// speedup vs baseline: 1.1748x; 1.0219x over previous
#include <cuda_runtime.h>
#include <cuda_bf16.h>
#include <cstdint>

#define N_NODES 100000
#define N_EDGES 1600000
#define D 32
#define ED 8
#define FULL 0xffffffffu
#define UN 4                 // 4-edge groups per tile -> 16 edges per warp-iter
#define TILE (UN * 4)        // N_EDGES % 16 == 0

// f32x2 packed-math helpers (PTX-only; ptxas never fuses these from C++).
#define PACKF2(out, lo, hi) \
    asm("mov.b64 %0, {%1, %2};" : "=l"(out) \
        : "r"(__float_as_uint(lo)), "r"(__float_as_uint(hi)))
#define FMA_F32X2(d, a, b, c) \
    asm("fma.rn.f32x2 %0, %1, %2, %3;" : "=l"(d) : "l"(a), "l"(b), "l"(c))
#define UNPACKF2(lo, hi, in) do { \
    uint32_t _l, _h; \
    asm("mov.b64 {%0, %1}, %2;" : "=r"(_l), "=r"(_h) : "l"(in)); \
    (lo) = __uint_as_float(_l); (hi) = __uint_as_float(_h); } while (0)

// Ping-pong node features + per-layer aggregation buffers (zeroed once).
__device__ float g_buf0[N_NODES * D];
__device__ float g_buf1[N_NODES * D];
__device__ float g_agg[3][N_NODES * D];

// ---------------------------------------------------------------------------
// Zero ALL three aggregation buffers in one pass (runs once per call).
// ---------------------------------------------------------------------------
__global__ void zero_all_kernel() {
    const int n4 = 3 * N_NODES * D / 4;
    float4* p = reinterpret_cast<float4*>(&g_agg[0][0]);
    float4 z = make_float4(0.f, 0.f, 0.f, 0.f);
    for (int i = blockIdx.x * blockDim.x + threadIdx.x; i < n4;
         i += gridDim.x * blockDim.x) {
        p[i] = z;
    }
}

// ---------------------------------------------------------------------------
// Edge kernel (R13 + streaming cache policy): 16 edges per warp-iteration,
// 4 independent 4-edge groups (MLP=4 gathers/REDs), next-tile idx prefetch,
// f32x2 packed FMA embedding loop.
//   lane layout: g = lane>>3 edge-in-quad, c = lane&7 column quad.
// edge_attr / edge_index are read exactly once per layer -> __ldcs
// (evict-first) so they stop evicting the reused x rows and agg lines
// from L2. Gathers keep the default caching policy.
// ---------------------------------------------------------------------------
__global__ __launch_bounds__(128, 4) void edge_kernel(
    const float* __restrict__ x_ext, int x_sel, int layer,
    const float* __restrict__ edge_attr,
    const float* __restrict__ We,   // layer slice: [8, 32]
    const float* __restrict__ be,   // layer slice: [32]
    const int*   __restrict__ edge_index)  // [2, E]: src rows then dst rows
{
    const float* x = (x_sel == 0) ? x_ext : (x_sel == 1 ? g_buf0 : g_buf1);
    float* agg = &g_agg[layer][0];

    const int lane = threadIdx.x & 31;
    const int c    = lane & 7;
    const int g    = lane >> 3;
    const int wid  = (blockIdx.x * blockDim.x + threadIdx.x) >> 5;
    const int nw   = (gridDim.x * blockDim.x) >> 5;

    // Weight column quads as packed f32x2 pairs: (x,y) and (z,w) per k.
    uint64_t wxy[ED], wzw[ED];
#pragma unroll
    for (int k = 0; k < ED; k++) {
        const float4 wv = *reinterpret_cast<const float4*>(We + k * D + c * 4);
        PACKF2(wxy[k], wv.x, wv.y);
        PACKF2(wzw[k], wv.z, wv.w);
    }
    uint64_t bxy, bzw;
    {
        const float4 bv = *reinterpret_cast<const float4*>(be + c * 4);
        PACKF2(bxy, bv.x, bv.y);
        PACKF2(bzw, bv.z, bv.w);
    }

    int e = wid * TILE;
    if (e >= N_EDGES) return;

    // lanes 0-15: src[e+lane]; lanes 16-31: dst[e+lane-16]
    const int idx_off = (lane < 16) ? lane : (N_EDGES - 16 + lane);

    // Prologue: first tile's indices in ONE streaming load.
    int s[UN], d[UN];
    {
        const int iv = __ldcs(edge_index + e + idx_off);
#pragma unroll
        for (int u = 0; u < UN; u++) {
            s[u] = __shfl_sync(FULL, iv, u * 4 + g);
            d[u] = __shfl_sync(FULL, iv, 16 + u * 4 + g);
        }
    }

    const int stride = nw * TILE;
    for (; e < N_EDGES; e += stride) {
        // 4 independent gathers issue immediately (indices resident).
        float4 xv[UN];
#pragma unroll
        for (int u = 0; u < UN; u++)
            xv[u] = __ldg(reinterpret_cast<const float4*>(
                x + (size_t)s[u] * D + c * 4));

        // Whole tile's 128 attr floats in one streaming LDG.128 (lane owns 4).
        const float4 av4 = __ldcs(
            reinterpret_cast<const float4*>(edge_attr + (size_t)e * ED) + lane);

        // Prefetch next tile's indices (wrapped on last iteration).
        const int ne = e + stride;
        const int nc = (ne < N_EDGES) ? ne : 0;
        const int niv = __ldcs(edge_index + nc + idx_off);

        // Packed-FMA embedding: a[u] = be + sum_k attr_k * We[k]
        // attr k of edge (4u+g) lives in lane 8u+2g+(k>>2), component k&3.
        uint64_t axy[UN], azw[UN];
#pragma unroll
        for (int u = 0; u < UN; u++) { axy[u] = bxy; azw[u] = bzw; }
#pragma unroll
        for (int k = 0; k < ED; k++) {
            const float comp = ((k & 3) == 0) ? av4.x
                             : ((k & 3) == 1) ? av4.y
                             : ((k & 3) == 2) ? av4.z : av4.w;
#pragma unroll
            for (int u = 0; u < UN; u++) {
                const float f =
                    __shfl_sync(FULL, comp, u * 8 + g * 2 + (k >> 2));
                uint64_t pf;
                PACKF2(pf, f, f);
                FMA_F32X2(axy[u], pf, wxy[k], axy[u]);
                FMA_F32X2(azw[u], pf, wzw[k], azw[u]);
            }
        }

#pragma unroll
        for (int u = 0; u < UN; u++) {
            float ax, ay, az, aw;
            UNPACKF2(ax, ay, axy[u]);
            UNPACKF2(az, aw, azw[u]);
            float4 m;
            m.x = fmaxf(xv[u].x + ax, 0.0f);
            m.y = fmaxf(xv[u].y + ay, 0.0f);
            m.z = fmaxf(xv[u].z + az, 0.0f);
            m.w = fmaxf(xv[u].w + aw, 0.0f);
            float* p = agg + (size_t)d[u] * D + c * 4;
            asm volatile("red.global.add.v4.f32 [%0], {%1,%2,%3,%4};"
                         :: "l"(p), "f"(m.x), "f"(m.y), "f"(m.z), "f"(m.w)
                         : "memory");
        }

        // Extract next tile's ids for the next iteration.
#pragma unroll
        for (int u = 0; u < UN; u++) {
            s[u] = __shfl_sync(FULL, niv, u * 4 + g);
            d[u] = __shfl_sync(FULL, niv, 16 + u * 4 + g);
        }
    }
}

// ---------------------------------------------------------------------------
// Node kernel: 2 nodes per warp, f32x2 FMAs (R13 form). agg read is dead
// after this kernel -> __ldcs so its lines don't linger in L2.
// ---------------------------------------------------------------------------
__global__ __launch_bounds__(128) void node_kernel(
    const float* __restrict__ x_ext, int x_sel, int layer,
    float* __restrict__ out_ext, int out_sel,
    const float* __restrict__ W,    // [32, 32]
    const float* __restrict__ b)    // [32]
{
    const float* x  = (x_sel == 0) ? x_ext : (x_sel == 1 ? g_buf0 : g_buf1);
    float* out = (out_sel == 0) ? out_ext : (out_sel == 1 ? g_buf0 : g_buf1);
    const float* agg = &g_agg[layer][0];

    const int lane = threadIdx.x & 31;
    const int c2   = lane & 15;     // column pair: cols 2c2, 2c2+1
    const int gn   = lane >> 4;     // node within the warp's pair
    const int wid  = (blockIdx.x * blockDim.x + threadIdx.x) >> 5;
    const int nw   = (gridDim.x * blockDim.x) >> 5;

    uint64_t w2[D];
#pragma unroll
    for (int k = 0; k < D; k++) {
        const float2 wv = *reinterpret_cast<const float2*>(W + k * D + c2 * 2);
        PACKF2(w2[k], wv.x, wv.y);
    }
    uint64_t b2;
    {
        const float2 bv = *reinterpret_cast<const float2*>(b + c2 * 2);
        PACKF2(b2, bv.x, bv.y);
    }

    for (int n2 = wid * 2; n2 < N_NODES; n2 += nw * 2) {
        const int node = n2 + gn;
        const float2 xv = *reinterpret_cast<const float2*>(
            x + (size_t)node * D + c2 * 2);
        const float2 ag = __ldcs(reinterpret_cast<const float2*>(
            agg + (size_t)node * D + c2 * 2));
        const float h0 = xv.x + ag.x;
        const float h1 = xv.y + ag.y;

        uint64_t acc = b2;
#pragma unroll
        for (int k = 0; k < D; k++) {
            const float hk = (k & 1) ? h1 : h0;
            const float f = __shfl_sync(FULL, hk, (gn << 4) + (k >> 1));
            uint64_t pf;
            PACKF2(pf, f, f);
            FMA_F32X2(acc, pf, w2[k], acc);
        }
        float o0, o1;
        UNPACKF2(o0, o1, acc);
        float2 o;
        o.x = fmaxf(o0, 0.01f * o0);    // leaky_relu 0.01
        o.y = fmaxf(o1, 0.01f * o1);
        *reinterpret_cast<float2*>(out + (size_t)node * D + c2 * 2) = o;
    }
}

// ---------------------------------------------------------------------------
extern "C" void kernel_launch(void* const* d_in, const int* in_sizes, int n_in,
                              void* d_out, int out_size)
{
    const float* x   = (const float*)d_in[0];   // [N, 32]
    const float* ea  = (const float*)d_in[1];   // [E, 8]
    const float* W   = (const float*)d_in[2];   // [3, 32, 32]
    const float* b   = (const float*)d_in[3];   // [3, 32]
    const float* We  = (const float*)d_in[4];   // [3, 8, 32]
    const float* be  = (const float*)d_in[5];   // [3, 32]
    const int*   ei  = (const int*)d_in[6];     // [2, E] int32
    float* out = (float*)d_out;

    const int x_sels[3]   = {0, 1, 2};
    const int out_sels[3] = {1, 2, 0};

    zero_all_kernel<<<1184, 256>>>();
    for (int l = 0; l < 3; l++) {
        edge_kernel<<<592, 128>>>(   // persistent: 4 blocks/SM, single wave
            x, x_sels[l], l, ea, We + l * ED * D, be + l * D, ei);
        node_kernel<<<1184, 128>>>(
            x, x_sels[l], l, out, out_sels[l], W + l * D * D, b + l * D);
    }
}

// round 15
// speedup vs baseline: 1.2019x; 1.0230x over previous
#include <cuda_runtime.h>
#include <cuda_bf16.h>
#include <cstdint>

#define N_NODES 100000
#define N_EDGES 1600000
#define D 32
#define ED 8
#define FULL 0xffffffffu
#define UN 4
#define TILE (UN * 4)            // 16 edges per tile
#define NTILES (N_EDGES / TILE)  // 100000

// f32x2 packed-math helpers (PTX-only).
#define PACKF2(out, lo, hi) \
    asm("mov.b64 %0, {%1, %2};" : "=l"(out) \
        : "r"(__float_as_uint(lo)), "r"(__float_as_uint(hi)))
#define FMA_F32X2(d, a, b, c) \
    asm("fma.rn.f32x2 %0, %1, %2, %3;" : "=l"(d) : "l"(a), "l"(b), "l"(c))
#define UNPACKF2(lo, hi, in) do { \
    uint32_t _l, _h; \
    asm("mov.b64 {%0, %1}, %2;" : "=r"(_l), "=r"(_h) : "l"(in)); \
    (lo) = __uint_as_float(_l); (hi) = __uint_as_float(_h); } while (0)

// Ping-pong node features + per-layer aggregation buffers (zeroed once).
__device__ float g_buf0[N_NODES * D];
__device__ float g_buf1[N_NODES * D];
__device__ float g_agg[3][N_NODES * D];

__global__ void zero_all_kernel() {
    const int n4 = 3 * N_NODES * D / 4;
    float4* p = reinterpret_cast<float4*>(&g_agg[0][0]);
    float4 z = make_float4(0.f, 0.f, 0.f, 0.f);
    for (int i = blockIdx.x * blockDim.x + threadIdx.x; i < n4;
         i += gridDim.x * blockDim.x) {
        p[i] = z;
    }
}

// ---------------------------------------------------------------------------
// Pipeline state for one 16-edge tile.
// ---------------------------------------------------------------------------
struct TileState {
    int s[UN], d[UN];
    float4 xv[UN];
    float4 av;
};

__device__ __forceinline__ void extract_ids(int iv, int g, TileState& ts) {
#pragma unroll
    for (int u = 0; u < UN; u++) {
        ts.s[u] = __shfl_sync(FULL, iv, u * 4 + g);
        ts.d[u] = __shfl_sync(FULL, iv, 16 + u * 4 + g);
    }
}

__device__ __forceinline__ void issue_loads(
    TileState& ts, int t, const float* __restrict__ x,
    const float* __restrict__ edge_attr, int c, int lane) {
#pragma unroll
    for (int u = 0; u < UN; u++)
        ts.xv[u] = __ldg(reinterpret_cast<const float4*>(
            x + (size_t)ts.s[u] * D + c * 4));
    ts.av = __ldcs(reinterpret_cast<const float4*>(
        edge_attr + (size_t)t * TILE * ED) + lane);
}

__device__ __forceinline__ void compute_red(
    const TileState& ts, float* __restrict__ agg,
    const uint64_t* wxy, const uint64_t* wzw, uint64_t bxy, uint64_t bzw,
    int c, int g) {
    uint64_t axy[UN], azw[UN];
#pragma unroll
    for (int u = 0; u < UN; u++) { axy[u] = bxy; azw[u] = bzw; }
#pragma unroll
    for (int k = 0; k < ED; k++) {
        const float comp = ((k & 3) == 0) ? ts.av.x
                         : ((k & 3) == 1) ? ts.av.y
                         : ((k & 3) == 2) ? ts.av.z : ts.av.w;
#pragma unroll
        for (int u = 0; u < UN; u++) {
            // attr k of edge (4u+g): lane 8u+2g+(k>>2), component k&3.
            const float f = __shfl_sync(FULL, comp, u * 8 + g * 2 + (k >> 2));
            uint64_t pf;
            PACKF2(pf, f, f);
            FMA_F32X2(axy[u], pf, wxy[k], axy[u]);
            FMA_F32X2(azw[u], pf, wzw[k], azw[u]);
        }
    }
#pragma unroll
    for (int u = 0; u < UN; u++) {
        float ax, ay, az, aw;
        UNPACKF2(ax, ay, axy[u]);
        UNPACKF2(az, aw, azw[u]);
        float4 m;
        m.x = fmaxf(ts.xv[u].x + ax, 0.0f);
        m.y = fmaxf(ts.xv[u].y + ay, 0.0f);
        m.z = fmaxf(ts.xv[u].z + az, 0.0f);
        m.w = fmaxf(ts.xv[u].w + aw, 0.0f);
        float* p = agg + (size_t)ts.d[u] * D + c * 4;
        asm volatile("red.global.add.v4.f32 [%0], {%1,%2,%3,%4};"
                     :: "l"(p), "f"(m.x), "f"(m.y), "f"(m.z), "f"(m.w)
                     : "memory");
    }
}

// ---------------------------------------------------------------------------
// Edge kernel: 2-stage ping-pong software pipeline over 16-edge tiles.
// Each body stages the NEXT tile's gathers + attr (ids from an index word
// loaded two bodies ahead) before computing/REDing the current tile, so all
// loads get a full body (~hundreds of cycles) to land before consumption.
// Warps own CONTIGUOUS tile ranges (streams idx/attr linearly).
// ---------------------------------------------------------------------------
__global__ __launch_bounds__(128, 4) void edge_kernel(
    const float* __restrict__ x_ext, int x_sel, int layer,
    const float* __restrict__ edge_attr,
    const float* __restrict__ We,   // layer slice: [8, 32]
    const float* __restrict__ be,   // layer slice: [32]
    const int*   __restrict__ edge_index)  // [2, E]
{
    const float* x = (x_sel == 0) ? x_ext : (x_sel == 1 ? g_buf0 : g_buf1);
    float* agg = &g_agg[layer][0];

    const int lane = threadIdx.x & 31;
    const int c    = lane & 7;
    const int g    = lane >> 3;
    const int wid  = (blockIdx.x * blockDim.x + threadIdx.x) >> 5;
    const int nw   = (gridDim.x * blockDim.x) >> 5;

    uint64_t wxy[ED], wzw[ED];
#pragma unroll
    for (int k = 0; k < ED; k++) {
        const float4 wv = *reinterpret_cast<const float4*>(We + k * D + c * 4);
        PACKF2(wxy[k], wv.x, wv.y);
        PACKF2(wzw[k], wv.z, wv.w);
    }
    uint64_t bxy, bzw;
    {
        const float4 bv = *reinterpret_cast<const float4*>(be + c * 4);
        PACKF2(bxy, bv.x, bv.y);
        PACKF2(bzw, bv.z, bv.w);
    }

    // Contiguous tile range for this warp.
    const int per = (NTILES + nw - 1) / nw;
    int t  = wid * per;
    const int t1 = min(t + per, NTILES);
    if (t >= t1) return;

    // lanes 0-15: src[...]; lanes 16-31: dst[...]
    const int idx_off = (lane < 16) ? lane : (N_EDGES - 16 + lane);

    TileState A, B;
    int ivA, ivB;

    // Prologue: stage tile t into A; prefetch idx for tile t+1.
    ivA = __ldcs(edge_index + t * TILE + idx_off);
    ivB = (t + 1 < t1) ? __ldcs(edge_index + (t + 1) * TILE + idx_off) : 0;
    extract_ids(ivA, g, A);
    issue_loads(A, t, x, edge_attr, c, lane);

    while (t + 1 < t1) {
        // --- body A: stage tile t+1 (B), consume tile t (A) ---
        extract_ids(ivB, g, B);
        issue_loads(B, t + 1, x, edge_attr, c, lane);
        ivA = (t + 2 < t1) ? __ldcs(edge_index + (t + 2) * TILE + idx_off) : 0;
        compute_red(A, agg, wxy, wzw, bxy, bzw, c, g);

        // --- body B: stage tile t+2 (A), consume tile t+1 (B) ---
        if (t + 2 < t1) {
            extract_ids(ivA, g, A);
            issue_loads(A, t + 2, x, edge_attr, c, lane);
            ivB = (t + 3 < t1) ? __ldcs(edge_index + (t + 3) * TILE + idx_off) : 0;
        }
        compute_red(B, agg, wxy, wzw, bxy, bzw, c, g);
        t += 2;
    }
    if (t < t1)   // odd-count tail: tile t already staged in A
        compute_red(A, agg, wxy, wzw, bxy, bzw, c, g);
}

// ---------------------------------------------------------------------------
// Node kernel: 2 nodes per warp, f32x2 FMAs, unrolled x2 (4 nodes per
// warp-iteration -> MLP=2 on x/agg loads, 2 independent FMA chains).
// ---------------------------------------------------------------------------
__global__ __launch_bounds__(128) void node_kernel(
    const float* __restrict__ x_ext, int x_sel, int layer,
    float* __restrict__ out_ext, int out_sel,
    const float* __restrict__ W,    // [32, 32]
    const float* __restrict__ b)    // [32]
{
    const float* x  = (x_sel == 0) ? x_ext : (x_sel == 1 ? g_buf0 : g_buf1);
    float* out = (out_sel == 0) ? out_ext : (out_sel == 1 ? g_buf0 : g_buf1);
    const float* agg = &g_agg[layer][0];

    const int lane = threadIdx.x & 31;
    const int c2   = lane & 15;     // column pair: cols 2c2, 2c2+1
    const int gn   = lane >> 4;     // node within a pair
    const int wid  = (blockIdx.x * blockDim.x + threadIdx.x) >> 5;
    const int nw   = (gridDim.x * blockDim.x) >> 5;

    uint64_t w2[D];
#pragma unroll
    for (int k = 0; k < D; k++) {
        const float2 wv = *reinterpret_cast<const float2*>(W + k * D + c2 * 2);
        PACKF2(w2[k], wv.x, wv.y);
    }
    uint64_t b2;
    {
        const float2 bv = *reinterpret_cast<const float2*>(b + c2 * 2);
        PACKF2(b2, bv.x, bv.y);
    }

    // N_NODES % 4 == 0: each warp-iteration covers 4 full nodes.
    for (int n4 = wid * 4; n4 < N_NODES; n4 += nw * 4) {
        const int nodeA = n4 + gn;
        const int nodeB = n4 + 2 + gn;

        const float2 xvA = *reinterpret_cast<const float2*>(
            x + (size_t)nodeA * D + c2 * 2);
        const float2 agA = __ldcs(reinterpret_cast<const float2*>(
            agg + (size_t)nodeA * D + c2 * 2));
        const float2 xvB = *reinterpret_cast<const float2*>(
            x + (size_t)nodeB * D + c2 * 2);
        const float2 agB = __ldcs(reinterpret_cast<const float2*>(
            agg + (size_t)nodeB * D + c2 * 2));

        const float hA0 = xvA.x + agA.x, hA1 = xvA.y + agA.y;
        const float hB0 = xvB.x + agB.x, hB1 = xvB.y + agB.y;

        uint64_t accA = b2, accB = b2;
#pragma unroll
        for (int k = 0; k < D; k++) {
            const float hkA = (k & 1) ? hA1 : hA0;
            const float hkB = (k & 1) ? hB1 : hB0;
            const float fA = __shfl_sync(FULL, hkA, (gn << 4) + (k >> 1));
            const float fB = __shfl_sync(FULL, hkB, (gn << 4) + (k >> 1));
            uint64_t pA, pB;
            PACKF2(pA, fA, fA);
            PACKF2(pB, fB, fB);
            FMA_F32X2(accA, pA, w2[k], accA);
            FMA_F32X2(accB, pB, w2[k], accB);
        }
        float a0, a1, b0, b1;
        UNPACKF2(a0, a1, accA);
        UNPACKF2(b0, b1, accB);
        float2 oA, oB;
        oA.x = fmaxf(a0, 0.01f * a0);
        oA.y = fmaxf(a1, 0.01f * a1);
        oB.x = fmaxf(b0, 0.01f * b0);
        oB.y = fmaxf(b1, 0.01f * b1);
        *reinterpret_cast<float2*>(out + (size_t)nodeA * D + c2 * 2) = oA;
        *reinterpret_cast<float2*>(out + (size_t)nodeB * D + c2 * 2) = oB;
    }
}

// ---------------------------------------------------------------------------
extern "C" void kernel_launch(void* const* d_in, const int* in_sizes, int n_in,
                              void* d_out, int out_size)
{
    const float* x   = (const float*)d_in[0];   // [N, 32]
    const float* ea  = (const float*)d_in[1];   // [E, 8]
    const float* W   = (const float*)d_in[2];   // [3, 32, 32]
    const float* b   = (const float*)d_in[3];   // [3, 32]
    const float* We  = (const float*)d_in[4];   // [3, 8, 32]
    const float* be  = (const float*)d_in[5];   // [3, 32]
    const int*   ei  = (const int*)d_in[6];     // [2, E] int32
    float* out = (float*)d_out;

    const int x_sels[3]   = {0, 1, 2};
    const int out_sels[3] = {1, 2, 0};

    zero_all_kernel<<<1184, 256>>>();
    for (int l = 0; l < 3; l++) {
        edge_kernel<<<592, 128>>>(   // persistent: 4 blocks/SM, single wave
            x, x_sels[l], l, ea, We + l * ED * D, be + l * D, ei);
        node_kernel<<<1184, 128>>>(
            x, x_sels[l], l, out, out_sels[l], W + l * D * D, b + l * D);
    }
}

// round 16
// speedup vs baseline: 1.2023x; 1.0003x over previous
#include <cuda_runtime.h>
#include <cuda_bf16.h>
#include <cstdint>

#define N_NODES 100000
#define N_EDGES 1600000
#define D 32
#define ED 8
#define FULL 0xffffffffu
#define UN 4                 // 4-edge groups per tile -> 16 edges per warp-iter
#define TILE (UN * 4)        // N_EDGES % 16 == 0

// f32x2 packed-math helpers (PTX-only; ptxas never fuses these from C++).
#define PACKF2(out, lo, hi) \
    asm("mov.b64 %0, {%1, %2};" : "=l"(out) \
        : "r"(__float_as_uint(lo)), "r"(__float_as_uint(hi)))
#define FMA_F32X2(d, a, b, c) \
    asm("fma.rn.f32x2 %0, %1, %2, %3;" : "=l"(d) : "l"(a), "l"(b), "l"(c))
#define UNPACKF2(lo, hi, in) do { \
    uint32_t _l, _h; \
    asm("mov.b64 {%0, %1}, %2;" : "=r"(_l), "=r"(_h) : "l"(in)); \
    (lo) = __uint_as_float(_l); (hi) = __uint_as_float(_h); } while (0)

// Ping-pong node features + per-layer aggregation buffers (zeroed once).
__device__ float g_buf0[N_NODES * D];
__device__ float g_buf1[N_NODES * D];
__device__ float g_agg[3][N_NODES * D];

// ---------------------------------------------------------------------------
// Zero ALL three aggregation buffers in one pass (runs once per call).
// ---------------------------------------------------------------------------
__global__ void zero_all_kernel() {
    const int n4 = 3 * N_NODES * D / 4;
    float4* p = reinterpret_cast<float4*>(&g_agg[0][0]);
    float4 z = make_float4(0.f, 0.f, 0.f, 0.f);
    for (int i = blockIdx.x * blockDim.x + threadIdx.x; i < n4;
         i += gridDim.x * blockDim.x) {
        p[i] = z;
    }
}

// ---------------------------------------------------------------------------
// Edge kernel (R14, measured best at 51.0us/layer): 16 edges per
// warp-iteration, 4 independent 4-edge groups (MLP=4 gathers/REDs),
// next-tile idx prefetch, f32x2 packed FMA embedding loop.
//   lane layout: g = lane>>3 edge-in-quad, c = lane&7 column quad.
// edge_attr / edge_index read once per layer -> __ldcs (evict-first).
// Persistent grid: 592 blocks (4/SM, single wave), strided tile loop.
// ---------------------------------------------------------------------------
__global__ __launch_bounds__(128, 4) void edge_kernel(
    const float* __restrict__ x_ext, int x_sel, int layer,
    const float* __restrict__ edge_attr,
    const float* __restrict__ We,   // layer slice: [8, 32]
    const float* __restrict__ be,   // layer slice: [32]
    const int*   __restrict__ edge_index)  // [2, E]: src rows then dst rows
{
    const float* x = (x_sel == 0) ? x_ext : (x_sel == 1 ? g_buf0 : g_buf1);
    float* agg = &g_agg[layer][0];

    const int lane = threadIdx.x & 31;
    const int c    = lane & 7;
    const int g    = lane >> 3;
    const int wid  = (blockIdx.x * blockDim.x + threadIdx.x) >> 5;
    const int nw   = (gridDim.x * blockDim.x) >> 5;

    // Weight column quads as packed f32x2 pairs: (x,y) and (z,w) per k.
    uint64_t wxy[ED], wzw[ED];
#pragma unroll
    for (int k = 0; k < ED; k++) {
        const float4 wv = *reinterpret_cast<const float4*>(We + k * D + c * 4);
        PACKF2(wxy[k], wv.x, wv.y);
        PACKF2(wzw[k], wv.z, wv.w);
    }
    uint64_t bxy, bzw;
    {
        const float4 bv = *reinterpret_cast<const float4*>(be + c * 4);
        PACKF2(bxy, bv.x, bv.y);
        PACKF2(bzw, bv.z, bv.w);
    }

    int e = wid * TILE;
    if (e >= N_EDGES) return;

    // lanes 0-15: src[e+lane]; lanes 16-31: dst[e+lane-16]
    const int idx_off = (lane < 16) ? lane : (N_EDGES - 16 + lane);

    // Prologue: first tile's indices in ONE streaming load.
    int s[UN], d[UN];
    {
        const int iv = __ldcs(edge_index + e + idx_off);
#pragma unroll
        for (int u = 0; u < UN; u++) {
            s[u] = __shfl_sync(FULL, iv, u * 4 + g);
            d[u] = __shfl_sync(FULL, iv, 16 + u * 4 + g);
        }
    }

    const int stride = nw * TILE;
    for (; e < N_EDGES; e += stride) {
        // 4 independent gathers issue immediately (indices resident).
        float4 xv[UN];
#pragma unroll
        for (int u = 0; u < UN; u++)
            xv[u] = __ldg(reinterpret_cast<const float4*>(
                x + (size_t)s[u] * D + c * 4));

        // Whole tile's 128 attr floats in one streaming LDG.128 (lane owns 4).
        const float4 av4 = __ldcs(
            reinterpret_cast<const float4*>(edge_attr + (size_t)e * ED) + lane);

        // Prefetch next tile's indices (wrapped on last iteration).
        const int ne = e + stride;
        const int nc = (ne < N_EDGES) ? ne : 0;
        const int niv = __ldcs(edge_index + nc + idx_off);

        // Packed-FMA embedding: a[u] = be + sum_k attr_k * We[k]
        // attr k of edge (4u+g) lives in lane 8u+2g+(k>>2), component k&3.
        uint64_t axy[UN], azw[UN];
#pragma unroll
        for (int u = 0; u < UN; u++) { axy[u] = bxy; azw[u] = bzw; }
#pragma unroll
        for (int k = 0; k < ED; k++) {
            const float comp = ((k & 3) == 0) ? av4.x
                             : ((k & 3) == 1) ? av4.y
                             : ((k & 3) == 2) ? av4.z : av4.w;
#pragma unroll
            for (int u = 0; u < UN; u++) {
                const float f =
                    __shfl_sync(FULL, comp, u * 8 + g * 2 + (k >> 2));
                uint64_t pf;
                PACKF2(pf, f, f);
                FMA_F32X2(axy[u], pf, wxy[k], axy[u]);
                FMA_F32X2(azw[u], pf, wzw[k], azw[u]);
            }
        }

#pragma unroll
        for (int u = 0; u < UN; u++) {
            float ax, ay, az, aw;
            UNPACKF2(ax, ay, axy[u]);
            UNPACKF2(az, aw, azw[u]);
            float4 m;
            m.x = fmaxf(xv[u].x + ax, 0.0f);
            m.y = fmaxf(xv[u].y + ay, 0.0f);
            m.z = fmaxf(xv[u].z + az, 0.0f);
            m.w = fmaxf(xv[u].w + aw, 0.0f);
            float* p = agg + (size_t)d[u] * D + c * 4;
            asm volatile("red.global.add.v4.f32 [%0], {%1,%2,%3,%4};"
                         :: "l"(p), "f"(m.x), "f"(m.y), "f"(m.z), "f"(m.w)
                         : "memory");
        }

        // Extract next tile's ids for the next iteration.
#pragma unroll
        for (int u = 0; u < UN; u++) {
            s[u] = __shfl_sync(FULL, niv, u * 4 + g);
            d[u] = __shfl_sync(FULL, niv, 16 + u * 4 + g);
        }
    }
}

// ---------------------------------------------------------------------------
// Node kernel (R15, measured best): 2 nodes per warp, f32x2 FMAs,
// unrolled x2 (4 nodes per warp-iteration -> MLP=2 on x/agg loads).
// ---------------------------------------------------------------------------
__global__ __launch_bounds__(128) void node_kernel(
    const float* __restrict__ x_ext, int x_sel, int layer,
    float* __restrict__ out_ext, int out_sel,
    const float* __restrict__ W,    // [32, 32]
    const float* __restrict__ b)    // [32]
{
    const float* x  = (x_sel == 0) ? x_ext : (x_sel == 1 ? g_buf0 : g_buf1);
    float* out = (out_sel == 0) ? out_ext : (out_sel == 1 ? g_buf0 : g_buf1);
    const float* agg = &g_agg[layer][0];

    const int lane = threadIdx.x & 31;
    const int c2   = lane & 15;     // column pair: cols 2c2, 2c2+1
    const int gn   = lane >> 4;     // node within a pair
    const int wid  = (blockIdx.x * blockDim.x + threadIdx.x) >> 5;
    const int nw   = (gridDim.x * blockDim.x) >> 5;

    uint64_t w2[D];
#pragma unroll
    for (int k = 0; k < D; k++) {
        const float2 wv = *reinterpret_cast<const float2*>(W + k * D + c2 * 2);
        PACKF2(w2[k], wv.x, wv.y);
    }
    uint64_t b2;
    {
        const float2 bv = *reinterpret_cast<const float2*>(b + c2 * 2);
        PACKF2(b2, bv.x, bv.y);
    }

    // N_NODES % 4 == 0: each warp-iteration covers 4 full nodes.
    for (int n4 = wid * 4; n4 < N_NODES; n4 += nw * 4) {
        const int nodeA = n4 + gn;
        const int nodeB = n4 + 2 + gn;

        const float2 xvA = *reinterpret_cast<const float2*>(
            x + (size_t)nodeA * D + c2 * 2);
        const float2 agA = __ldcs(reinterpret_cast<const float2*>(
            agg + (size_t)nodeA * D + c2 * 2));
        const float2 xvB = *reinterpret_cast<const float2*>(
            x + (size_t)nodeB * D + c2 * 2);
        const float2 agB = __ldcs(reinterpret_cast<const float2*>(
            agg + (size_t)nodeB * D + c2 * 2));

        const float hA0 = xvA.x + agA.x, hA1 = xvA.y + agA.y;
        const float hB0 = xvB.x + agB.x, hB1 = xvB.y + agB.y;

        uint64_t accA = b2, accB = b2;
#pragma unroll
        for (int k = 0; k < D; k++) {
            const float hkA = (k & 1) ? hA1 : hA0;
            const float hkB = (k & 1) ? hB1 : hB0;
            const float fA = __shfl_sync(FULL, hkA, (gn << 4) + (k >> 1));
            const float fB = __shfl_sync(FULL, hkB, (gn << 4) + (k >> 1));
            uint64_t pA, pB;
            PACKF2(pA, fA, fA);
            PACKF2(pB, fB, fB);
            FMA_F32X2(accA, pA, w2[k], accA);
            FMA_F32X2(accB, pB, w2[k], accB);
        }
        float a0, a1, b0, b1;
        UNPACKF2(a0, a1, accA);
        UNPACKF2(b0, b1, accB);
        float2 oA, oB;
        oA.x = fmaxf(a0, 0.01f * a0);   // leaky_relu 0.01
        oA.y = fmaxf(a1, 0.01f * a1);
        oB.x = fmaxf(b0, 0.01f * b0);
        oB.y = fmaxf(b1, 0.01f * b1);
        *reinterpret_cast<float2*>(out + (size_t)nodeA * D + c2 * 2) = oA;
        *reinterpret_cast<float2*>(out + (size_t)nodeB * D + c2 * 2) = oB;
    }
}

// ---------------------------------------------------------------------------
extern "C" void kernel_launch(void* const* d_in, const int* in_sizes, int n_in,
                              void* d_out, int out_size)
{
    const float* x   = (const float*)d_in[0];   // [N, 32]
    const float* ea  = (const float*)d_in[1];   // [E, 8]
    const float* W   = (const float*)d_in[2];   // [3, 32, 32]
    const float* b   = (const float*)d_in[3];   // [3, 32]
    const float* We  = (const float*)d_in[4];   // [3, 8, 32]
    const float* be  = (const float*)d_in[5];   // [3, 32]
    const int*   ei  = (const int*)d_in[6];     // [2, E] int32
    float* out = (float*)d_out;

    const int x_sels[3]   = {0, 1, 2};
    const int out_sels[3] = {1, 2, 0};

    zero_all_kernel<<<1184, 256>>>();
    for (int l = 0; l < 3; l++) {
        edge_kernel<<<592, 128>>>(   // persistent: 4 blocks/SM, single wave
            x, x_sels[l], l, ea, We + l * ED * D, be + l * D, ei);
        node_kernel<<<1184, 128>>>(
            x, x_sels[l], l, out, out_sels[l], W + l * D * D, b + l * D);
    }
}